// round 7
// baseline (speedup 1.0000x reference)
#include <cuda_runtime.h>

#define BB 20
#define LL 20
#define VV 100000
#define NP (BB * LL * LL)     // 8000 gathered elements
#define NPROD 25              // producer blocks (blocks 1..25), 320 elems each

__device__ float    g_P[NP];  // gathered P scratch (32 KB)
__device__ unsigned g_flag;   // zero-init; producers count up, block 0 resets

#define PAD_LO 288
#define PAD_HI 192

// ---------------------------------------------------------------------------
// Single kernel, intra-grid producer/consumer (26 co-resident blocks):
//   blocks 1..25: gather 320 scattered elements each -> g_P, publish via
//     threadfence + syncthreads + one atomicAdd (canonical pattern).
//   block 0: pre-computes labels/ballots/constants while producers run,
//     tid0 acquire-polls the counter to 25, resets it, then runs the
//     anti-diagonal wavefront DP (10 warps; warp w = batches {2w,2w+1} in
//     16-lane segments; lane c owns DP columns 2c+1, 2c+2; one segmented
//     shfl per step, diag = previous step's left).
// ---------------------------------------------------------------------------
__global__ void __launch_bounds__(320) calcs_pc_kernel(
    const float* __restrict__ topic_prob,
    const int*   __restrict__ hard_label,
    float*       __restrict__ out)
{
    const int tid = threadIdx.x;

    if (blockIdx.x != 0) {
        // ---------------- producers ----------------
        const int i = (blockIdx.x - 1) * 320 + tid;
        const int b = i / (LL * LL);
        const int j = (i / LL) % LL;
        const int k = i % LL;
        const int lab = __ldg(&hard_label[b * LL + k]);
        const int idx = lab < 0 ? 0 : (lab > (VV - 1) ? (VV - 1) : lab);
        g_P[i] = __ldg(&topic_prob[(size_t)(b * LL + j) * VV + idx]);
        __threadfence();
        __syncthreads();
        if (tid == 0) atomicAdd(&g_flag, 1u);
        return;
    }

    // ---------------- consumer: block 0 ----------------
    __shared__ float4 s_buf4[(PAD_LO + NP + PAD_HI) / 4];
    __shared__ float  s_loss[BB];
    float* s_P = ((float*)s_buf4) + PAD_LO;

    const int warp = tid >> 5;
    const int lane = tid & 31;
    const int sub  = lane & 15;
    const int half = lane >> 4;

    // pre-work overlapping the producers (nothing touches g_P yet)
    const int b0 = 2 * warp, b1 = 2 * warp + 1;
    const int l0 = (lane < LL) ? __ldg(&hard_label[b0 * LL + lane]) : -1;
    const unsigned bal0 = __ballot_sync(0xFFFFFFFFu, (lane < LL) && (l0 >= 0));
    const int l1 = (lane < LL) ? __ldg(&hard_label[b1 * LL + lane]) : -1;
    const unsigned bal1 = __ballot_sync(0xFFFFFFFFu, (lane < LL) && (l1 >= 0));

    const unsigned bal = half ? bal1 : bal0;
    const int len = __popc(bal & 0xFFFFFu);
    const int b   = half ? b1 : b0;
    const int c   = sub;

    const int  base  = b * (LL * LL) - 18 * c - LL;   // s_P index at t=0
    const bool capA  = (2 * c + 1 == len);
    const bool capB  = (2 * c + 2 == len);
    const bool valid = (c < 10);

    // wait for all producers (acquire pairs with their fence+atomic release)
    if (tid == 0) {
        unsigned v;
        do {
            asm volatile("ld.global.acquire.gpu.u32 %0, [%1];"
                         : "=r"(v) : "l"(&g_flag) : "memory");
        } while (v < NPROD);
        asm volatile("st.global.relaxed.gpu.u32 [%0], %1;"
                     :: "l"(&g_flag), "r"(0u) : "memory");  // reset for replay
    }
    __syncthreads();   // broadcast acquire to whole block

    // warp-local staging: this warp's two batches (200 float4), L2-hot
    {
        const float4* __restrict__ src = ((const float4*)g_P) + b0 * 100;
        float4* dst = (float4*)(s_P + b0 * (LL * LL));
        #pragma unroll
        for (int i = lane; i < 200; i += 32)
            dst[i] = src[i];
    }
    __syncwarp();

    float prevA = 0.0f, prevB = 0.0f, dleft = 0.0f, result = 0.0f;

    if (bal0 == 0xFFFFFu && bal1 == 0xFFFFFu) {
        // fast path: all masks set (always for this data)
        #pragma unroll
        for (int t = 1; t <= LL + 9; ++t) {
            float left = __shfl_up_sync(0xFFFFFFFFu, prevB, 1, 16);
            if (sub == 0) left = 0.0f;
            const float diag = dleft;
            dleft = left;

            const int  j   = t - c;
            const bool act = valid && (j >= 1) && (j <= LL);

            const float2 p2 = *(const float2*)(s_P + base + t * LL);

            const float Ma = fmaxf(left, prevA);
            const float vA = fmaf(p2.x, diag + 1.0f - Ma, Ma);
            const float Mb = fmaxf(vA, prevB);
            const float vB = fmaf(p2.y, prevA + 1.0f - Mb, Mb);

            if (act) {
                if (j == len) {
                    if (capA) result = vA;
                    if (capB) result = vB;
                }
                prevA = vA;
                prevB = vB;
            }
        }
    } else {
        // general path: per-cell mask zeroing
        const unsigned bitA = (bal >> (2 * c)) & 1u;
        const unsigned bitB = (bal >> (2 * c + 1)) & 1u;
        #pragma unroll
        for (int t = 1; t <= LL + 9; ++t) {
            float left = __shfl_up_sync(0xFFFFFFFFu, prevB, 1, 16);
            if (sub == 0) left = 0.0f;
            const float diag = dleft;
            dleft = left;

            const int  j   = t - c;
            const bool act = valid && (j >= 1) && (j <= LL);
            const int  js  = (j < 1) ? 1 : (j > LL ? LL : j);
            const unsigned mj = (bal >> (js - 1)) & 1u;

            const float2 p2 = *(const float2*)(s_P + base + t * LL);

            const float Ma = fmaxf(left, prevA);
            float vA = fmaf(p2.x, diag + 1.0f - Ma, Ma);
            vA = (mj & bitA) ? vA : 0.0f;
            const float Mb = fmaxf(vA, prevB);
            float vB = fmaf(p2.y, prevA + 1.0f - Mb, Mb);
            vB = (mj & bitB) ? vB : 0.0f;

            if (act) {
                if (j == len) {
                    if (capA) result = vA;
                    if (capB) result = vB;
                }
                prevA = vA;
                prevB = vB;
            }
        }
    }

    if (len > 0) {
        if ((capA || capB) && valid)
            s_loss[b] = -logf(result / (float)len);
    } else if (sub == 0) {
        s_loss[b] = -logf(0.0f / 0.0f);   // 0/0 -> nan, matches reference
    }
    __syncthreads();

    if (warp == 0) {
        float v = (lane < BB) ? s_loss[lane] : 0.0f;
        #pragma unroll
        for (int off = 16; off > 0; off >>= 1)
            v += __shfl_down_sync(0xFFFFFFFFu, v, off);
        if (lane == 0) out[0] = v * (1.0f / (float)BB);
    }
}

extern "C" void kernel_launch(void* const* d_in, const int* in_sizes, int n_in,
                              void* d_out, int out_size) {
    const float* topic_prob = (const float*)d_in[0];
    const int*   hard_label = (const int*)d_in[1];
    float*       out        = (float*)d_out;
    calcs_pc_kernel<<<NPROD + 1, 320>>>(topic_prob, hard_label, out);
}

// round 9
// speedup vs baseline: 1.2316x; 1.2316x over previous
#include <cuda_runtime.h>
#include <cstdint>

#define BB 20
#define LL 20
#define VV 100000
#define NP (BB * LL * LL)     // 8000 gathered elements
#define CSZ 8                 // cluster size (portable max)
#define PER_CTA (NP / CSZ)    // 1000 elements per CTA

#define PAD_LO 288
#define PAD_HI 192

// ---------------------------------------------------------------------------
// One 8-CTA cluster. Every CTA gathers 1000 scattered elements (spreads the
// divergent 128B-line traffic across 8 SMs' L1tex queues) and writes the
// results DIRECTLY into CTA 0's shared memory via mapa + st.shared::cluster
// (no global scratch, no threadfence, no atomics). Cluster barrier
// (release/acquire) orders the DSMEM stores; ranks 1..7 exit; rank 0 runs
// the anti-diagonal wavefront DP on its now-populated smem:
//   10 warps; warp w = batches {2w, 2w+1} in 16-lane segments; lane c owns
//   DP columns 2c+1, 2c+2; one segmented shfl per step (diag = prior left).
// ---------------------------------------------------------------------------
__global__ void __cluster_dims__(CSZ, 1, 1) __launch_bounds__(320)
calcs_cluster_kernel(
    const float* __restrict__ topic_prob,
    const int*   __restrict__ hard_label,
    float*       __restrict__ out)
{
    __shared__ float4 s_buf4[(PAD_LO + NP + PAD_HI) / 4];
    __shared__ float  s_loss[BB];
    float* s_P = ((float*)s_buf4) + PAD_LO;

    const int tid = threadIdx.x;
    unsigned int rank;
    asm("mov.u32 %0, %%cluster_ctarank;" : "=r"(rank));

    // smem address of s_P in THIS cta, then map to rank 0's window
    unsigned int laddr;
    asm("{ .reg .u64 t; cvta.to.shared.u64 t, %1; cvt.u32.u64 %0, t; }"
        : "=r"(laddr) : "l"((void*)s_P));
    unsigned int raddr0;
    asm("mapa.shared::cluster.u32 %0, %1, 0;" : "=r"(raddr0) : "r"(laddr));

    // ---- distributed gather -> DSMEM store into rank 0's s_P ----
    {
        const int base = (int)rank * PER_CTA;
        #pragma unroll
        for (int it = 0; it < 4; ++it) {
            const int rel = tid + it * 320;
            if (rel < PER_CTA) {                 // 3 full passes + tail (tid<40)
                const int i = base + rel;
                const int b = i / (LL * LL);
                const int j = (i / LL) % LL;
                const int k = i % LL;
                const int lab = __ldg(&hard_label[b * LL + k]);
                const int idx = lab < 0 ? 0 : (lab > (VV - 1) ? (VV - 1) : lab);
                const float v = __ldg(&topic_prob[(size_t)(b * LL + j) * VV + idx]);
                asm volatile("st.shared::cluster.f32 [%0], %1;"
                             :: "r"(raddr0 + 4u * (unsigned int)i), "f"(v) : "memory");
            }
        }
    }

    // cluster barrier: release DSMEM stores / acquire before rank 0 reads
    asm volatile("barrier.cluster.arrive.aligned;" ::: "memory");
    asm volatile("barrier.cluster.wait.aligned;" ::: "memory");

    if (rank != 0) return;                       // producers done

    // ---------------- rank 0: wavefront DP ----------------
    const int warp = tid >> 5;
    const int lane = tid & 31;
    const int sub  = lane & 15;
    const int half = lane >> 4;

    const int b0 = 2 * warp, b1 = 2 * warp + 1;
    const int l0 = (lane < LL) ? __ldg(&hard_label[b0 * LL + lane]) : -1;
    const unsigned bal0 = __ballot_sync(0xFFFFFFFFu, (lane < LL) && (l0 >= 0));
    const int l1 = (lane < LL) ? __ldg(&hard_label[b1 * LL + lane]) : -1;
    const unsigned bal1 = __ballot_sync(0xFFFFFFFFu, (lane < LL) && (l1 >= 0));

    const unsigned bal = half ? bal1 : bal0;
    const int len = __popc(bal & 0xFFFFFu);
    const int b   = half ? b1 : b0;
    const int c   = sub;

    const int  base  = b * (LL * LL) - 18 * c - LL;   // s_P index at t=0
    const bool capA  = (2 * c + 1 == len);
    const bool capB  = (2 * c + 2 == len);
    const bool valid = (c < 10);

    float prevA = 0.0f, prevB = 0.0f, dleft = 0.0f, result = 0.0f;

    if (bal0 == 0xFFFFFu && bal1 == 0xFFFFFu) {
        // fast path: all masks set (always for this data)
        #pragma unroll
        for (int t = 1; t <= LL + 9; ++t) {
            float left = __shfl_up_sync(0xFFFFFFFFu, prevB, 1, 16);
            if (sub == 0) left = 0.0f;
            const float diag = dleft;
            dleft = left;

            const int  j   = t - c;
            const bool act = valid && (j >= 1) && (j <= LL);

            const float2 p2 = *(const float2*)(s_P + base + t * LL);

            const float Ma = fmaxf(left, prevA);
            const float vA = fmaf(p2.x, diag + 1.0f - Ma, Ma);
            const float Mb = fmaxf(vA, prevB);
            const float vB = fmaf(p2.y, prevA + 1.0f - Mb, Mb);

            if (act) {
                if (j == len) {
                    if (capA) result = vA;
                    if (capB) result = vB;
                }
                prevA = vA;
                prevB = vB;
            }
        }
    } else {
        // general path: per-cell mask zeroing
        const unsigned bitA = (bal >> (2 * c)) & 1u;
        const unsigned bitB = (bal >> (2 * c + 1)) & 1u;
        #pragma unroll
        for (int t = 1; t <= LL + 9; ++t) {
            float left = __shfl_up_sync(0xFFFFFFFFu, prevB, 1, 16);
            if (sub == 0) left = 0.0f;
            const float diag = dleft;
            dleft = left;

            const int  j   = t - c;
            const bool act = valid && (j >= 1) && (j <= LL);
            const int  js  = (j < 1) ? 1 : (j > LL ? LL : j);
            const unsigned mj = (bal >> (js - 1)) & 1u;

            const float2 p2 = *(const float2*)(s_P + base + t * LL);

            const float Ma = fmaxf(left, prevA);
            float vA = fmaf(p2.x, diag + 1.0f - Ma, Ma);
            vA = (mj & bitA) ? vA : 0.0f;
            const float Mb = fmaxf(vA, prevB);
            float vB = fmaf(p2.y, prevA + 1.0f - Mb, Mb);
            vB = (mj & bitB) ? vB : 0.0f;

            if (act) {
                if (j == len) {
                    if (capA) result = vA;
                    if (capB) result = vB;
                }
                prevA = vA;
                prevB = vB;
            }
        }
    }

    if (len > 0) {
        if ((capA || capB) && valid)
            s_loss[b] = -logf(result / (float)len);
    } else if (sub == 0) {
        s_loss[b] = -logf(0.0f / 0.0f);   // 0/0 -> nan, matches reference
    }
    __syncthreads();

    if (warp == 0) {
        float v = (lane < BB) ? s_loss[lane] : 0.0f;
        #pragma unroll
        for (int off = 16; off > 0; off >>= 1)
            v += __shfl_down_sync(0xFFFFFFFFu, v, off);
        if (lane == 0) out[0] = v * (1.0f / (float)BB);
    }
}

extern "C" void kernel_launch(void* const* d_in, const int* in_sizes, int n_in,
                              void* d_out, int out_size) {
    const float* topic_prob = (const float*)d_in[0];
    const int*   hard_label = (const int*)d_in[1];
    float*       out        = (float*)d_out;
    calcs_cluster_kernel<<<CSZ, 320>>>(topic_prob, hard_label, out);
}